// round 7
// baseline (speedup 1.0000x reference)
#include <cuda_runtime.h>

#define T_LEN   1000
#define NB      4
#define GRIDB   128
#define THREADS 768

typedef unsigned long long ull;

__device__ float g_xg[512 * T_LEN * 256];   // precomputed input projections (+biases)

__device__ __forceinline__ ull fma2(ull a, ull b, ull c) {
    ull d;
    asm("fma.rn.f32x2 %0, %1, %2, %3;" : "=l"(d) : "l"(a), "l"(b), "l"(c));
    return d;
}
__device__ __forceinline__ ull pack2(float lo, float hi) {
    ull d;
    asm("mov.b64 %0, {%1, %2};" : "=l"(d) : "f"(lo), "f"(hi));
    return d;
}
__device__ __forceinline__ float hadd(ull a) {
    float lo, hi;
    asm("mov.b64 {%0, %1}, %2;" : "=f"(lo), "=f"(hi) : "l"(a));
    return lo + hi;
}
__device__ __forceinline__ float tanhap(float x) {
    float y;
    asm("tanh.approx.f32 %0, %1;" : "=f"(y) : "f"(x));
    return y;
}
__device__ __forceinline__ float sigap(float x) {
    return fmaf(0.5f, tanhap(0.5f * x), 0.5f);
}

// ---------------- pass 1: xg[b][t][j] = b_ih1[j]+b_hh1[j] + sum_k w_ih1[j][k]*x[b][k][t]
extern "C" __global__ void __launch_bounds__(256)
xg_kernel(const float* __restrict__ x, const float* __restrict__ w_ih1,
          const float* __restrict__ b_ih1, const float* __restrict__ b_hh1)
{
    __shared__ float xt[26 * 100];
    const int tt = blockIdx.x;          // t-tile (0..9), 100 steps each
    const int b  = blockIdx.y;          // batch
    const int j  = threadIdx.x;         // gate row 0..255
    const int t0 = tt * 100;

    const float* xb = x + (size_t)b * 26 * T_LEN;
    for (int idx = j; idx < 26 * 100; idx += 256) {
        const int k = idx / 100, i = idx - k * 100;
        xt[idx] = xb[k * T_LEN + t0 + i];
    }
    float w[26];
    #pragma unroll
    for (int k = 0; k < 26; ++k) w[k] = w_ih1[j * 26 + k];
    const float bias = b_ih1[j] + b_hh1[j];
    __syncthreads();

    float* og = g_xg + ((size_t)b * T_LEN + t0) * 256 + j;
    #pragma unroll 4
    for (int i = 0; i < 100; ++i) {
        float a = bias;
        #pragma unroll
        for (int k = 0; k < 26; ++k) a = fmaf(w[k], xt[k * 100 + i], a);
        og[(size_t)i * 256] = a;
    }
}

// ---------------- pass 2: persistent recurrent kernel ----------------
// tid 0..511  : LSTM1 gate rows. warp w (0..15), lane = kh(1b)|rloc(4b):
//               row = w*16+rloc (0..255), kh-half of k in {0,1}. 16 ull weights.
// tid 512..767: LSTM2 gate rows. warp w (16..23): row = (w-16)*16+rloc (0..127),
//               48-element k-half. 24 ull weights.
// Phase B (state update): lanes 0..15 of EVERY warp, u = wid*16+rloc (0..383):
//               u<256 -> LSTM1 unit (b=u>>6, n=u&63); else LSTM2 (b,n of u-256).
// v1s padded: h1[n] stored at n + 4*(n>=32) so the two kh broadcast addresses
// of one LDS.128 land on disjoint banks (1 wavefront).
extern "C" __global__ void __launch_bounds__(THREADS, 1)
lstm_kernel(const float* __restrict__ w_hh1,
            const float* __restrict__ w_ih2, const float* __restrict__ w_hh2,
            const float* __restrict__ b_ih2, const float* __restrict__ b_hh2,
            const float* __restrict__ w_fc1, const float* __restrict__ b_fc1,
            const float* __restrict__ w_fc2, const float* __restrict__ b_fc2,
            float* __restrict__ out)
{
    __shared__ __align__(16) float v1s[NB * 68];   // h1, padded (68 = 64+4)
    __shared__ __align__(16) float v2s[NB * 96];   // [h1(64) | h2(32)]
    __shared__ float g1s[NB * 256];
    __shared__ float g2s[NB * 128];
    __shared__ float fcs[64];

    const int tid  = threadIdx.x;
    const int b0   = blockIdx.x * NB;
    const int wid  = tid >> 5;
    const int lane = tid & 31;
    const bool is1 = tid < 512;
    const int kh   = lane >> 4;
    const int rloc = lane & 15;
    const int row  = is1 ? (wid * 16 + rloc) : ((wid - 16) * 16 + rloc);

    // ----- per-thread gate-row weights (packed f32x2) -----
    ull W[24];
    float bias2 = 0.f;
    if (is1) {
        const float* wr = w_hh1 + row * 64 + kh * 32;
        #pragma unroll
        for (int i = 0; i < 16; ++i) W[i] = pack2(wr[2 * i], wr[2 * i + 1]);
    } else {
        float wt[48];
        #pragma unroll
        for (int k = 0; k < 48; ++k) {
            const int kk = kh * 48 + k;
            wt[k] = (kk < 64) ? w_ih2[row * 64 + kk] : w_hh2[row * 32 + (kk - 64)];
        }
        #pragma unroll
        for (int i = 0; i < 24; ++i) W[i] = pack2(wt[2 * i], wt[2 * i + 1]);
        bias2 = b_ih2[row] + b_hh2[row];
    }

    for (int e = tid; e < NB * 68; e += THREADS) v1s[e] = 0.f;
    for (int e = tid; e < NB * 96; e += THREADS) v2s[e] = 0.f;

    // ----- phase-B role: one update per (lane 0..15) of every warp -----
    const bool upd = (kh == 0);
    const int u   = wid * 16 + rloc;            // 0..383
    const int ub  = (u < 256) ? (u >> 6) : ((u - 256) >> 5);
    const int un  = (u < 256) ? (u & 63) : ((u - 256) & 31);
    float cst = 0.f;

    // ----- xg prefetch (LSTM1 kh==0 lanes) -----
    const bool xthr = is1 && (kh == 0);
    const float* xgp = g_xg + (size_t)b0 * T_LEN * 256 + row;
    const size_t BS = (size_t)T_LEN * 256;
    float xr[4] = {0.f, 0.f, 0.f, 0.f};
    if (xthr) {
        #pragma unroll
        for (int b = 0; b < 4; ++b) xr[b] = xgp[b * BS];
    }

    __syncthreads();

    // iter t: phase A computes gates1(t) and gates2(t-1); phase B applies both updates.
    #pragma unroll 1
    for (int t = 0; t <= T_LEN; ++t) {
        if (is1 && t < T_LEN) {
            float nx[4];
            const int tp = (t + 1 < T_LEN) ? t + 1 : 0;
            if (xthr) {
                #pragma unroll
                for (int b = 0; b < 4; ++b) nx[b] = xgp[(size_t)tp * 256 + b * BS];
            }
            const float* vb = v1s + kh * 36;           // bank-disjoint halves
            ull a0 = 0, a1 = 0, a2 = 0, a3 = 0;
            #pragma unroll
            for (int q = 0; q < 8; ++q) {
                ulonglong2 v;
                v = *(const ulonglong2*)(vb + 0 * 68 + q * 4);
                a0 = fma2(W[2 * q], v.x, a0); a0 = fma2(W[2 * q + 1], v.y, a0);
                v = *(const ulonglong2*)(vb + 1 * 68 + q * 4);
                a1 = fma2(W[2 * q], v.x, a1); a1 = fma2(W[2 * q + 1], v.y, a1);
                v = *(const ulonglong2*)(vb + 2 * 68 + q * 4);
                a2 = fma2(W[2 * q], v.x, a2); a2 = fma2(W[2 * q + 1], v.y, a2);
                v = *(const ulonglong2*)(vb + 3 * 68 + q * 4);
                a3 = fma2(W[2 * q], v.x, a3); a3 = fma2(W[2 * q + 1], v.y, a3);
            }
            float p0 = hadd(a0), p1 = hadd(a1), p2 = hadd(a2), p3 = hadd(a3);
            p0 += __shfl_xor_sync(0xffffffffu, p0, 16);
            p1 += __shfl_xor_sync(0xffffffffu, p1, 16);
            p2 += __shfl_xor_sync(0xffffffffu, p2, 16);
            p3 += __shfl_xor_sync(0xffffffffu, p3, 16);
            if (kh == 0) {
                g1s[0 * 256 + row] = p0 + xr[0];
                g1s[1 * 256 + row] = p1 + xr[1];
                g1s[2 * 256 + row] = p2 + xr[2];
                g1s[3 * 256 + row] = p3 + xr[3];
                xr[0] = nx[0]; xr[1] = nx[1]; xr[2] = nx[2]; xr[3] = nx[3];
            }
        } else if (!is1) {
            const float* vb = v2s + kh * 48;           // banks already disjoint
            ull a0 = 0, a1 = 0, a2 = 0, a3 = 0;
            #pragma unroll
            for (int q = 0; q < 12; ++q) {
                ulonglong2 v;
                v = *(const ulonglong2*)(vb + 0 * 96 + q * 4);
                a0 = fma2(W[2 * q], v.x, a0); a0 = fma2(W[2 * q + 1], v.y, a0);
                v = *(const ulonglong2*)(vb + 1 * 96 + q * 4);
                a1 = fma2(W[2 * q], v.x, a1); a1 = fma2(W[2 * q + 1], v.y, a1);
                v = *(const ulonglong2*)(vb + 2 * 96 + q * 4);
                a2 = fma2(W[2 * q], v.x, a2); a2 = fma2(W[2 * q + 1], v.y, a2);
                v = *(const ulonglong2*)(vb + 3 * 96 + q * 4);
                a3 = fma2(W[2 * q], v.x, a3); a3 = fma2(W[2 * q + 1], v.y, a3);
            }
            float p0 = hadd(a0), p1 = hadd(a1), p2 = hadd(a2), p3 = hadd(a3);
            p0 += __shfl_xor_sync(0xffffffffu, p0, 16);
            p1 += __shfl_xor_sync(0xffffffffu, p1, 16);
            p2 += __shfl_xor_sync(0xffffffffu, p2, 16);
            p3 += __shfl_xor_sync(0xffffffffu, p3, 16);
            if (kh == 0) {
                g2s[0 * 128 + row] = p0 + bias2;
                g2s[1 * 128 + row] = p1 + bias2;
                g2s[2 * 128 + row] = p2 + bias2;
                g2s[3 * 128 + row] = p3 + bias2;
            }
        }
        __syncthreads();                        // gates complete; v reusable

        if (upd) {
            if (u < 256) {
                if (t < T_LEN) {
                    const float gi = g1s[ub * 256 +       un];
                    const float gf = g1s[ub * 256 +  64 + un];
                    const float gg = g1s[ub * 256 + 128 + un];
                    const float go = g1s[ub * 256 + 192 + un];
                    const float ii = sigap(gi), ff = sigap(gf);
                    const float g  = tanhap(gg), oo = sigap(go);
                    cst = ff * cst + ii * g;
                    const float h = oo * tanhap(cst);
                    v1s[ub * 68 + un + ((un >> 5) << 2)] = h;
                    v2s[ub * 96 + un] = h;
                }
            } else if (t > 0) {
                const float gi = g2s[ub * 128 +      un];
                const float gf = g2s[ub * 128 + 32 + un];
                const float gg = g2s[ub * 128 + 64 + un];
                const float go = g2s[ub * 128 + 96 + un];
                const float ii = sigap(gi), ff = sigap(gf);
                const float g  = tanhap(gg), oo = sigap(go);
                cst = ff * cst + ii * g;
                v2s[ub * 96 + 64 + un] = oo * tanhap(cst);
            }
        }
        __syncthreads();                        // state ready for next iter
    }

    // ----- FC head on final h2 = v2s[b][64..95] -----
    if (tid < 64) {
        const int b = tid >> 4, f = tid & 15;
        float a = __ldg(b_fc1 + f);
        #pragma unroll
        for (int k = 0; k < 32; ++k)
            a += __ldg(w_fc1 + f * 32 + k) * v2s[b * 96 + 64 + k];
        fcs[b * 16 + f] = fmaxf(a, 0.f);
    }
    __syncthreads();
    if (tid < 40) {
        const int b = tid / 10, o = tid - b * 10;
        float a = __ldg(b_fc2 + o);
        #pragma unroll
        for (int k = 0; k < 16; ++k)
            a += __ldg(w_fc2 + o * 16 + k) * fcs[b * 16 + k];
        out[(b0 + b) * 10 + o] = a;
    }
}

extern "C" void kernel_launch(void* const* d_in, const int* in_sizes, int n_in,
                              void* d_out, int out_size) {
    (void)in_sizes; (void)n_in; (void)out_size;
    xg_kernel<<<dim3(10, 512), 256>>>(
        (const float*)d_in[0],   // x
        (const float*)d_in[1],   // w_ih1
        (const float*)d_in[3],   // b_ih1
        (const float*)d_in[4]);  // b_hh1
    lstm_kernel<<<GRIDB, THREADS>>>(
        (const float*)d_in[2],   // w_hh1
        (const float*)d_in[5],   // w_ih2
        (const float*)d_in[6],   // w_hh2
        (const float*)d_in[7],   // b_ih2
        (const float*)d_in[8],   // b_hh2
        (const float*)d_in[9],   // w_fc1
        (const float*)d_in[10],  // b_fc1
        (const float*)d_in[11],  // w_fc2
        (const float*)d_in[12],  // b_fc2
        (float*)d_out);
}

// round 8
// speedup vs baseline: 1.3857x; 1.3857x over previous
#include <cuda_runtime.h>

#define T_LEN   1000
#define NB      4
#define GRIDB   128
#define THREADS 384

typedef unsigned long long ull;

__device__ float g_xg[512 * T_LEN * 256];   // precomputed input projections (+biases)

__device__ __forceinline__ ull fma2(ull a, ull b, ull c) {
    ull d;
    asm("fma.rn.f32x2 %0, %1, %2, %3;" : "=l"(d) : "l"(a), "l"(b), "l"(c));
    return d;
}
__device__ __forceinline__ ull pack2(float lo, float hi) {
    ull d;
    asm("mov.b64 %0, {%1, %2};" : "=l"(d) : "f"(lo), "f"(hi));
    return d;
}
__device__ __forceinline__ float hadd(ull a) {
    float lo, hi;
    asm("mov.b64 {%0, %1}, %2;" : "=f"(lo), "=f"(hi) : "l"(a));
    return lo + hi;
}
__device__ __forceinline__ float tanhap(float x) {
    float y;
    asm("tanh.approx.f32 %0, %1;" : "=f"(y) : "f"(x));
    return y;
}
__device__ __forceinline__ float sigap(float x) {
    return fmaf(0.5f, tanhap(0.5f * x), 0.5f);
}

// ---------------- pass 1: xg[b][t][j] = b_ih1[j]+b_hh1[j] + sum_k w_ih1[j][k]*x[b][k][t]
extern "C" __global__ void __launch_bounds__(256)
xg_kernel(const float* __restrict__ x, const float* __restrict__ w_ih1,
          const float* __restrict__ b_ih1, const float* __restrict__ b_hh1)
{
    __shared__ float xt[26 * 100];
    const int tt = blockIdx.x;          // t-tile (0..9), 100 steps each
    const int b  = blockIdx.y;          // batch
    const int j  = threadIdx.x;         // gate row 0..255
    const int t0 = tt * 100;

    const float* xb = x + (size_t)b * 26 * T_LEN;
    for (int idx = j; idx < 26 * 100; idx += 256) {
        const int k = idx / 100, i = idx - k * 100;
        xt[idx] = xb[k * T_LEN + t0 + i];
    }
    float w[26];
    #pragma unroll
    for (int k = 0; k < 26; ++k) w[k] = w_ih1[j * 26 + k];
    const float bias = b_ih1[j] + b_hh1[j];
    __syncthreads();

    float* og = g_xg + ((size_t)b * T_LEN + t0) * 256 + j;
    #pragma unroll 4
    for (int i = 0; i < 100; ++i) {
        float a = bias;
        #pragma unroll
        for (int k = 0; k < 26; ++k) a = fmaf(w[k], xt[k * 100 + i], a);
        og[(size_t)i * 256] = a;
    }
}

// ---------------- pass 2: persistent recurrent kernel, unit-parallel org ----------------
// Thread = (unit n, k-quarter kq). lane = nloc*4 + kq.
//   warps 0..7  : LSTM1, n = wid*8+nloc (0..63), k-slice [kq*16, kq*16+16) of h1
//   warps 8..11 : LSTM2, n = (wid-8)*8+nloc (0..31), k-slice [kq*24, +24) of [h1|h2]
// Each thread accumulates 4 gates x 4 batches partials; a 12-shfl butterfly leaves
// lane kq with the FULL 4 gate sums for batch b=kq; it updates c,h in registers and
// stores h. No gate SMEM, one barrier per step, ping-pong v buffers.
// v1 layout: batch b at b*80, k-slice kq at +kq*20 (banks 0/20/8/28 — disjoint).
// v2 layout: batch b at b*96, [h1(64)|h2(32)] (slices 0/24/48/72 — banks disjoint).
extern "C" __global__ void __launch_bounds__(THREADS, 1)
lstm_kernel(const float* __restrict__ w_hh1,
            const float* __restrict__ w_ih2, const float* __restrict__ w_hh2,
            const float* __restrict__ b_ih2, const float* __restrict__ b_hh2,
            const float* __restrict__ w_fc1, const float* __restrict__ b_fc1,
            const float* __restrict__ w_fc2, const float* __restrict__ b_fc2,
            float* __restrict__ out)
{
    __shared__ __align__(16) float v1s[2][NB * 80];
    __shared__ __align__(16) float v2s[2][NB * 96];
    __shared__ float fcs[64];

    const int tid  = threadIdx.x;
    const int b0   = blockIdx.x * NB;
    const int wid  = tid >> 5;
    const int lane = tid & 31;
    const bool is1 = wid < 8;
    const int nloc = lane >> 2;
    const int kq   = lane & 3;
    const int n    = is1 ? (wid * 8 + nloc) : ((wid - 8) * 8 + nloc);
    const int q0   = kq & 1, q1 = (kq >> 1) & 1;

    // ----- per-thread weights: 4 gates x k-slice, packed f32x2 -----
    ull W[48];
    float bias2[4];
    if (is1) {
        #pragma unroll
        for (int g = 0; g < 4; ++g) {
            const float* wr = w_hh1 + (g * 64 + n) * 64 + kq * 16;
            #pragma unroll
            for (int j = 0; j < 8; ++j) W[g * 8 + j] = pack2(wr[2 * j], wr[2 * j + 1]);
        }
    } else {
        #pragma unroll
        for (int g = 0; g < 4; ++g) {
            #pragma unroll
            for (int j = 0; j < 12; ++j) {
                const int kk = kq * 24 + 2 * j;   // even; pairs never straddle 64
                float lo, hi;
                if (kk < 64) {
                    lo = w_ih2[(g * 32 + n) * 64 + kk];
                    hi = w_ih2[(g * 32 + n) * 64 + kk + 1];
                } else {
                    lo = w_hh2[(g * 32 + n) * 32 + kk - 64];
                    hi = w_hh2[(g * 32 + n) * 32 + kk - 63];
                }
                W[g * 12 + j] = pack2(lo, hi);
            }
            bias2[g] = b_ih2[g * 32 + n] + b_hh2[g * 32 + n];
        }
    }

    for (int e = tid; e < 2 * NB * 80; e += THREADS) ((float*)v1s)[e] = 0.f;
    for (int e = tid; e < 2 * NB * 96; e += THREADS) ((float*)v2s)[e] = 0.f;

    // xg pointer for (batch kq, unit n): value at [t][g*64+n]
    const float* xq = g_xg + (size_t)(b0 + kq) * T_LEN * 256 + n;
    float xr[4];
    if (is1) {
        #pragma unroll
        for (int g = 0; g < 4; ++g) xr[g] = xq[g * 64];
    }

    float c = 0.f;
    __syncthreads();

    // iter t: LSTM1 computes step t (t<T_LEN); LSTM2 computes step t-1 (t>0).
    #pragma unroll 1
    for (int t = 0; t <= T_LEN; ++t) {
        const int cur = t & 1, nxt = cur ^ 1;
        if (is1) {
            if (t < T_LEN) {
                // prefetch xg(t+1)
                const int tp = (t + 1 < T_LEN) ? t + 1 : T_LEN - 1;
                float nx[4];
                #pragma unroll
                for (int g = 0; g < 4; ++g) nx[g] = xq[(size_t)tp * 256 + g * 64];

                ull A[4][4];
                #pragma unroll
                for (int g = 0; g < 4; ++g)
                    #pragma unroll
                    for (int b = 0; b < 4; ++b) A[g][b] = 0;
                const float* vb = v1s[cur] + kq * 20;
                #pragma unroll
                for (int b = 0; b < 4; ++b) {
                    const ulonglong2 ua = *(const ulonglong2*)(vb + b * 80 + 0);
                    const ulonglong2 ub = *(const ulonglong2*)(vb + b * 80 + 4);
                    const ulonglong2 uc = *(const ulonglong2*)(vb + b * 80 + 8);
                    const ulonglong2 ud = *(const ulonglong2*)(vb + b * 80 + 12);
                    #pragma unroll
                    for (int g = 0; g < 4; ++g) {
                        ull a = A[g][b];
                        a = fma2(W[g * 8 + 0], ua.x, a); a = fma2(W[g * 8 + 1], ua.y, a);
                        a = fma2(W[g * 8 + 2], ub.x, a); a = fma2(W[g * 8 + 3], ub.y, a);
                        a = fma2(W[g * 8 + 4], uc.x, a); a = fma2(W[g * 8 + 5], uc.y, a);
                        a = fma2(W[g * 8 + 6], ud.x, a); a = fma2(W[g * 8 + 7], ud.y, a);
                        A[g][b] = a;
                    }
                }
                // butterfly reduce over kq: lane kq ends with full sums for batch kq
                float fin[4];
                #pragma unroll
                for (int g = 0; g < 4; ++g) {
                    const float s0 = hadd(A[g][0]), s1 = hadd(A[g][1]);
                    const float s2 = hadd(A[g][2]), s3 = hadd(A[g][3]);
                    const float kp0 = q0 ? s1 : s0, sd0 = q0 ? s0 : s1;
                    const float kp1 = q0 ? s3 : s2, sd1 = q0 ? s2 : s3;
                    const float k10 = kp0 + __shfl_xor_sync(0xffffffffu, sd0, 1);
                    const float k11 = kp1 + __shfl_xor_sync(0xffffffffu, sd1, 1);
                    const float kp = q1 ? k11 : k10, sd = q1 ? k10 : k11;
                    fin[g] = kp + __shfl_xor_sync(0xffffffffu, sd, 2);
                }
                // in-register LSTM1 update for (n, batch kq)
                const float gi = sigap(fin[0] + xr[0]);
                const float gf = sigap(fin[1] + xr[1]);
                const float gg = tanhap(fin[2] + xr[2]);
                const float go = sigap(fin[3] + xr[3]);
                c = gf * c + gi * gg;
                const float h = go * tanhap(c);
                v1s[nxt][kq * 80 + (n >> 4) * 20 + (n & 15)] = h;
                v2s[nxt][kq * 96 + n] = h;
                #pragma unroll
                for (int g = 0; g < 4; ++g) xr[g] = nx[g];
            }
        } else if (t > 0) {
            ull A[4][4];
            #pragma unroll
            for (int g = 0; g < 4; ++g)
                #pragma unroll
                for (int b = 0; b < 4; ++b) A[g][b] = 0;
            const float* vb = v2s[cur] + kq * 24;
            #pragma unroll
            for (int b = 0; b < 4; ++b) {
                const ulonglong2 ua = *(const ulonglong2*)(vb + b * 96 + 0);
                const ulonglong2 ub = *(const ulonglong2*)(vb + b * 96 + 4);
                const ulonglong2 uc = *(const ulonglong2*)(vb + b * 96 + 8);
                const ulonglong2 ud = *(const ulonglong2*)(vb + b * 96 + 12);
                const ulonglong2 ue = *(const ulonglong2*)(vb + b * 96 + 16);
                const ulonglong2 uf = *(const ulonglong2*)(vb + b * 96 + 20);
                #pragma unroll
                for (int g = 0; g < 4; ++g) {
                    ull a = A[g][b];
                    a = fma2(W[g * 12 + 0],  ua.x, a); a = fma2(W[g * 12 + 1],  ua.y, a);
                    a = fma2(W[g * 12 + 2],  ub.x, a); a = fma2(W[g * 12 + 3],  ub.y, a);
                    a = fma2(W[g * 12 + 4],  uc.x, a); a = fma2(W[g * 12 + 5],  uc.y, a);
                    a = fma2(W[g * 12 + 6],  ud.x, a); a = fma2(W[g * 12 + 7],  ud.y, a);
                    a = fma2(W[g * 12 + 8],  ue.x, a); a = fma2(W[g * 12 + 9],  ue.y, a);
                    a = fma2(W[g * 12 + 10], uf.x, a); a = fma2(W[g * 12 + 11], uf.y, a);
                    A[g][b] = a;
                }
            }
            float fin[4];
            #pragma unroll
            for (int g = 0; g < 4; ++g) {
                const float s0 = hadd(A[g][0]), s1 = hadd(A[g][1]);
                const float s2 = hadd(A[g][2]), s3 = hadd(A[g][3]);
                const float kp0 = q0 ? s1 : s0, sd0 = q0 ? s0 : s1;
                const float kp1 = q0 ? s3 : s2, sd1 = q0 ? s2 : s3;
                const float k10 = kp0 + __shfl_xor_sync(0xffffffffu, sd0, 1);
                const float k11 = kp1 + __shfl_xor_sync(0xffffffffu, sd1, 1);
                const float kp = q1 ? k11 : k10, sd = q1 ? k10 : k11;
                fin[g] = kp + __shfl_xor_sync(0xffffffffu, sd, 2);
            }
            const float gi = sigap(fin[0] + bias2[0]);
            const float gf = sigap(fin[1] + bias2[1]);
            const float gg = tanhap(fin[2] + bias2[2]);
            const float go = sigap(fin[3] + bias2[3]);
            c = gf * c + gi * gg;
            v2s[nxt][kq * 96 + 64 + n] = go * tanhap(c);
        }
        __syncthreads();        // nxt complete; cur reusable
    }

    // ----- FC head on final h2 = v2s[1][b][64..95] -----
    if (tid < 64) {
        const int b = tid >> 4, f = tid & 15;
        float a = __ldg(b_fc1 + f);
        #pragma unroll
        for (int k = 0; k < 32; ++k)
            a += __ldg(w_fc1 + f * 32 + k) * v2s[1][b * 96 + 64 + k];
        fcs[b * 16 + f] = fmaxf(a, 0.f);
    }
    __syncthreads();
    if (tid < 40) {
        const int b = tid / 10, o = tid - b * 10;
        float a = __ldg(b_fc2 + o);
        #pragma unroll
        for (int k = 0; k < 16; ++k)
            a += __ldg(w_fc2 + o * 16 + k) * fcs[b * 16 + k];
        out[(b0 + b) * 10 + o] = a;
    }
}

extern "C" void kernel_launch(void* const* d_in, const int* in_sizes, int n_in,
                              void* d_out, int out_size) {
    (void)in_sizes; (void)n_in; (void)out_size;
    xg_kernel<<<dim3(10, 512), 256>>>(
        (const float*)d_in[0],   // x
        (const float*)d_in[1],   // w_ih1
        (const float*)d_in[3],   // b_ih1
        (const float*)d_in[4]);  // b_hh1
    lstm_kernel<<<GRIDB, THREADS>>>(
        (const float*)d_in[2],   // w_hh1
        (const float*)d_in[5],   // w_ih2
        (const float*)d_in[6],   // w_hh2
        (const float*)d_in[7],   // b_ih2
        (const float*)d_in[8],   // b_hh2
        (const float*)d_in[9],   // w_fc1
        (const float*)d_in[10],  // b_fc1
        (const float*)d_in[11],  // w_fc2
        (const float*)d_in[12],  // b_fc2
        (float*)d_out);
}